// round 17
// baseline (speedup 1.0000x reference)
#include <cuda_runtime.h>
#include <cuda_fp16.h>
#include <cstdint>

// ---------------------------------------------------------------------------
// Problem constants
// ---------------------------------------------------------------------------
constexpr int Bq = 2, Tq = 2048, Cq = 1024, Hq = 16, Dq = 64;
constexpr int Mrows = Bq * Tq;      // 4096
constexpr int N_QKV = 3 * Cq;       // 3072

// Scratch (device globals — no allocation allowed). All fp16 operands.
__device__ __half g_q[Bq * Hq * Tq * Dq];   // [B,H,T,D]
__device__ __half g_k[Bq * Hq * Tq * Dq];   // [B,H,T,D]
__device__ __half g_v[Bq * Hq * Tq * Dq];   // [B,H,T,D]
__device__ __half g_y[Bq * Tq * Cq];        // [B,T,C]
__device__ __half g_xr[Mrows * Cq];         // x in fp16
__device__ __half g_wqkv_h[Cq * N_QKV];     // Wqkv fp16, natural [C, 3C]
__device__ __half g_wo_h[Cq * Cq];          // Wo fp16, natural [C, C]

// ---------------------------------------------------------------------------
// Helpers
// ---------------------------------------------------------------------------
__device__ __forceinline__ void mma16(float* d, const uint32_t* a, const uint32_t* b) {
    asm volatile(
        "mma.sync.aligned.m16n8k16.row.col.f32.f16.f16.f32 "
        "{%0,%1,%2,%3}, {%4,%5,%6,%7}, {%8,%9}, {%0,%1,%2,%3};\n"
        : "+f"(d[0]), "+f"(d[1]), "+f"(d[2]), "+f"(d[3])
        : "r"(a[0]), "r"(a[1]), "r"(a[2]), "r"(a[3]), "r"(b[0]), "r"(b[1]));
}

#define LDM_X4(r0, r1, r2, r3, addr) \
    asm volatile("ldmatrix.sync.aligned.m8n8.x4.shared.b16 {%0,%1,%2,%3}, [%4];" \
        : "=r"(r0), "=r"(r1), "=r"(r2), "=r"(r3) : "r"(addr))

#define LDM_X4_T(r0, r1, r2, r3, addr) \
    asm volatile("ldmatrix.sync.aligned.m8n8.x4.trans.shared.b16 {%0,%1,%2,%3}, [%4];" \
        : "=r"(r0), "=r"(r1), "=r"(r2), "=r"(r3) : "r"(addr))

__device__ __forceinline__ void cpasync16(uint32_t dst, const void* src) {
    asm volatile("cp.async.cg.shared.global [%0], [%1], 16;" :: "r"(dst), "l"(src));
}
#define CP_COMMIT() asm volatile("cp.async.commit_group;" ::: "memory")
#define CP_WAIT1()  asm volatile("cp.async.wait_group 1;" ::: "memory")
#define CP_WAIT0()  asm volatile("cp.async.wait_group 0;" ::: "memory")

__device__ __forceinline__ uint32_t pack_h2(float x, float y) {
    __half2 h = __float22half2_rn(make_float2(x, y));
    return *(uint32_t*)&h;
}

// ---------------------------------------------------------------------------
// Preprocess: fused fp32 -> fp16 rounding of x, Wqkv, Wo (16 elems/thread)
// ---------------------------------------------------------------------------
constexpr int NF16_X  = Mrows * Cq / 16;       // 262144
constexpr int NF16_W1 = Cq * N_QKV / 16;       // 196608
constexpr int NF16_W2 = Cq * Cq / 16;          // 65536
constexpr int NF16_TOT = NF16_X + NF16_W1 + NF16_W2;   // 524288

__global__ __launch_bounds__(256) void round_all(const float* __restrict__ x,
                                                 const float* __restrict__ wqkv,
                                                 const float* __restrict__ wo) {
    int i = blockIdx.x * 256 + threadIdx.x;
    const float* src;
    __half* dst;
    int j;
    if (i < NF16_X)               { src = x;    dst = g_xr;     j = i; }
    else if (i < NF16_X + NF16_W1){ src = wqkv; dst = g_wqkv_h; j = i - NF16_X; }
    else                          { src = wo;   dst = g_wo_h;   j = i - NF16_X - NF16_W1; }
    float4 v0 = ((const float4*)src)[4 * j];
    float4 v1 = ((const float4*)src)[4 * j + 1];
    float4 v2 = ((const float4*)src)[4 * j + 2];
    float4 v3 = ((const float4*)src)[4 * j + 3];
    uint4 o0, o1;
    o0.x = pack_h2(v0.x, v0.y); o0.y = pack_h2(v0.z, v0.w);
    o0.z = pack_h2(v1.x, v1.y); o0.w = pack_h2(v1.z, v1.w);
    o1.x = pack_h2(v2.x, v2.y); o1.y = pack_h2(v2.z, v2.w);
    o1.z = pack_h2(v3.x, v3.y); o1.w = pack_h2(v3.z, v3.w);
    ((uint4*)dst)[2 * j] = o0;
    ((uint4*)dst)[2 * j + 1] = o1;
}

// ---------------------------------------------------------------------------
// fp16 mma.sync GEMM (R15 champion): CTA 128x256, BK=128, 8 warps, warp tile
// 64x64, 1 CTA/SM, 2-stage cp.async, one barrier per chunk.
// ---------------------------------------------------------------------------
constexpr int A_STG_B = 32768;
constexpr int G_STG_B = 98304;
constexpr int GEMM_SMEM = 2 * G_STG_B;        // 196608

__global__ void __launch_bounds__(256, 1) gemm_mma(const __half* __restrict__ A,
                                                   const __half* __restrict__ W,
                                                   int Ktot, int Ntot, int mode,
                                                   const float* __restrict__ bias,
                                                   float* __restrict__ outp) {
    extern __shared__ char smc[];
    const int tid = threadIdx.x, lane = tid & 31, wid = tid >> 5;
    const int wm = wid >> 2, wn = wid & 3;
    const int m0 = blockIdx.y * 128, n0 = blockIdx.x * 256;
    const int lj = lane & 3, lr4 = lane >> 2;
    const uint32_t sbase = (uint32_t)__cvta_generic_to_shared(smc);

    const int a_row = wm * 64 + ((lane >> 3) & 1) * 8 + (lane & 7);
    const int a_hi = lane >> 4;
    const int bt_row = ((lane >> 3) & 1) * 8 + (lane & 7);
    const int bt_hi = lane >> 4;

    float d[4][8][4];
#pragma unroll
    for (int mi = 0; mi < 4; mi++)
#pragma unroll
        for (int ni = 0; ni < 8; ni++)
#pragma unroll
            for (int e = 0; e < 4; e++) d[mi][ni][e] = 0.f;

    const int nc = Ktot / 128;

    auto stage_copy = [&](int c, int stg) {
        const uint32_t base = sbase + stg * G_STG_B;
#pragma unroll
        for (int s = 0; s < 8; s++) {
            int id = tid + 256 * s;
            int row = id >> 4, u = id & 15;
            uint32_t phys = row * 256 + (((u & 8) | ((u ^ (row & 7)) & 7)) * 16);
            cpasync16(base + phys, A + (size_t)(m0 + row) * Ktot + c * 128 + u * 8);
        }
#pragma unroll
        for (int s = 0; s < 16; s++) {
            int id = tid + 256 * s;
            int row = id >> 5, u = id & 31;
            uint32_t phys = row * 512 + (((u & 24) | ((u ^ (row & 7)) & 7)) * 16);
            cpasync16(base + A_STG_B + phys,
                      W + (size_t)(c * 128 + row) * Ntot + n0 + u * 8);
        }
    };

    stage_copy(0, 0); CP_COMMIT();

    for (int c = 0; c < nc; c++) {
        CP_WAIT0();
        __syncthreads();
        if (c + 1 < nc) {
            stage_copy(c + 1, (c + 1) & 1);
            CP_COMMIT();
        }

        const uint32_t abase = sbase + (c & 1) * G_STG_B;
        const uint32_t bbase = abase + A_STG_B;
#pragma unroll
        for (int ks = 0; ks < 8; ks++) {
            uint32_t a[4][4], b[8][2];
#pragma unroll
            for (int mi = 0; mi < 4; mi++) {
                int row = a_row + mi * 16;
                int u = ks * 2 + a_hi;
                uint32_t addr = abase + row * 256 +
                                (((u & 8) | ((u ^ (row & 7)) & 7)) * 16);
                LDM_X4(a[mi][0], a[mi][1], a[mi][2], a[mi][3], addr);
            }
            {
                int row = bt_row + ks * 16;
                uint32_t rowoff = bbase + row * 512;
                int rlow = row & 7;
#pragma unroll
                for (int p = 0; p < 4; p++) {
                    int u = wn * 8 + 2 * p + bt_hi;
                    uint32_t addr = rowoff + (((u & 24) | ((u ^ rlow) & 7)) * 16);
                    LDM_X4_T(b[2 * p][0], b[2 * p][1],
                             b[2 * p + 1][0], b[2 * p + 1][1], addr);
                }
            }
#pragma unroll
            for (int mi = 0; mi < 4; mi++)
#pragma unroll
                for (int ni = 0; ni < 8; ni++) mma16(d[mi][ni], a[mi], b[ni]);
        }
    }

    // epilogue
#pragma unroll
    for (int mi = 0; mi < 4; mi++) {
#pragma unroll
        for (int half = 0; half < 2; half++) {
            int m = m0 + wm * 64 + mi * 16 + lr4 + half * 8;
            int bb = m >> 11, t = m & (Tq - 1);
#pragma unroll
            for (int ni = 0; ni < 8; ni++) {
                int n = n0 + wn * 64 + ni * 8 + 2 * lj;
                float vx = d[mi][ni][half * 2 + 0];
                float vy = d[mi][ni][half * 2 + 1];
                if (mode == 0) {
                    int which = n >> 10, cc = n & (Cq - 1);
                    int hh = cc >> 6, dd = cc & 63;
                    __half* dst = (which == 0) ? g_q : (which == 1) ? g_k : g_v;
                    uint32_t hv = pack_h2(vx, vy);
                    *(uint32_t*)(dst + ((size_t)(bb * Hq + hh) * Tq + t) * Dq + dd) = hv;
                } else {
                    vx += __ldg(bias + n);
                    vy += __ldg(bias + n + 1);
                    *(float2*)(outp + (size_t)m * Cq + n) = make_float2(vx, vy);
                }
            }
        }
    }
}

// ---------------------------------------------------------------------------
// fp16 warp-MMA flash attention (causal), static-shift softmax.
// 128 q-rows/CTA, 4 warps x 32 rows, 3-stage cp.async, 1 barrier per tile.
// NEW vs R16: (1) row-sum l on scalar pipes (FADD+SHFL) instead of ones-MMA
// — MMA issue is the binding resource now; (2) warp-level early-out on fully
// masked diagonal tiles.
// ---------------------------------------------------------------------------
constexpr int FSTG_B = 16384;              // K 8KB + V 8KB per stage
constexpr int FLASH_SMEM = 3 * FSTG_B;     // 49152
constexpr float LOG2E = 1.44269504f;
constexpr float SHIFT2 = 4.0f * 1.44269504f;   // shift in log2 domain

__global__ void __launch_bounds__(128, 2) flash_mma() {
    extern __shared__ char smc[];
    const int tid = threadIdx.x, lane = tid & 31, wid = tid >> 5;   // 4 warps
    const int bh = blockIdx.y;
    const int q0 = (gridDim.x - 1 - blockIdx.x) * 128;   // longest blocks first
    const int bb = bh >> 4, h = bh & 15;
    const int lj = lane & 3, lr4 = lane >> 2;
    const uint32_t sbase = (uint32_t)__cvta_generic_to_shared(smc);

    const __half* kbase = g_k + (size_t)bh * Tq * Dq;
    const __half* vbase = g_v + (size_t)bh * Tq * Dq;

    // Q fragments for 2 m-tiles (32 rows/warp); scale = 0.125*log2e folded in
    uint32_t qa[2][4][4];
#pragma unroll
    for (int mi2 = 0; mi2 < 2; mi2++) {
        const __half2 sc = __float2half2_rn(0.125f * LOG2E);
        const __half* r0p = g_q + ((size_t)bh * Tq + q0 + wid * 32 + mi2 * 16 + lr4) * Dq;
        const __half* r1p = r0p + 8 * Dq;
#pragma unroll
        for (int ks = 0; ks < 4; ks++) {
            int c = ks * 16 + 2 * lj;
            __half2 v0 = __hmul2(*(const __half2*)(r0p + c), sc);
            __half2 v1 = __hmul2(*(const __half2*)(r1p + c), sc);
            __half2 v2 = __hmul2(*(const __half2*)(r0p + c + 8), sc);
            __half2 v3 = __hmul2(*(const __half2*)(r1p + c + 8), sc);
            qa[mi2][ks][0] = *(uint32_t*)&v0; qa[mi2][ks][1] = *(uint32_t*)&v1;
            qa[mi2][ks][2] = *(uint32_t*)&v2; qa[mi2][ks][3] = *(uint32_t*)&v3;
        }
    }

    float o[2][8][4];
#pragma unroll
    for (int mi2 = 0; mi2 < 2; mi2++)
#pragma unroll
        for (int ni = 0; ni < 8; ni++)
#pragma unroll
            for (int e = 0; e < 4; e++) o[mi2][ni][e] = 0.f;
    float l[2][2] = { {0.f, 0.f}, {0.f, 0.f} };   // [mi2][rowgrp a/b]
    const int row_base = q0 + wid * 32;           // warp's first q row
    const int row_a0 = row_base + lr4;
    const int cc = 2 * lj;

    // ldmatrix lane addressing
    const int k_row = ((lane >> 4) & 1) * 8 + (lane & 7);   // + p*16
    const int k_hi = (lane >> 3) & 1;
    const int v_row = ((lane >> 3) & 1) * 8 + (lane & 7);   // + ks*16
    const int v_hi = lane >> 4;

    const int ntile = q0 / 64 + 2;

    auto issue_tile = [&](int ti, int stg) {
        const uint32_t kd = sbase + stg * FSTG_B;
        const uint32_t vd = kd + 8192;
        const int j0 = ti * 64;
#pragma unroll
        for (int s = 0; s < 4; s++) {
            int id = tid + 128 * s;           // 0..511
            int row = id >> 3, u = id & 7;
            uint32_t off = row * 128 + ((u ^ (row & 7)) * 16);
            cpasync16(kd + off, kbase + (size_t)(j0 + row) * Dq + u * 8);
            cpasync16(vd + off, vbase + (size_t)(j0 + row) * Dq + u * 8);
        }
    };

    issue_tile(0, 0); CP_COMMIT();
    if (ntile > 1) issue_tile(1, 1);
    CP_COMMIT();

    int st = 0;
    for (int ti = 0; ti < ntile; ti++) {
        const int j0 = ti * 64;
        CP_WAIT1();
        __syncthreads();                      // single barrier per tile
        int wst = st + 2; if (wst >= 3) wst -= 3;
        if (ti + 2 < ntile) issue_tile(ti + 2, wst);
        CP_COMMIT();

        // warp-level early-out: tile entirely above this warp's causal row range
        if (j0 < row_base + 32) {
            const uint32_t kstg = sbase + st * FSTG_B;
            const uint32_t vstg = kstg + 8192;

            // S = Q K^T  (accumulators pre-biased with -SHIFT2)
            float s[2][8][4];
#pragma unroll
            for (int mi2 = 0; mi2 < 2; mi2++)
#pragma unroll
                for (int ni = 0; ni < 8; ni++)
#pragma unroll
                    for (int e = 0; e < 4; e++) s[mi2][ni][e] = -SHIFT2;
#pragma unroll
            for (int ks = 0; ks < 4; ks++) {
#pragma unroll
                for (int p = 0; p < 4; p++) {
                    int row = k_row + p * 16;
                    uint32_t addr = kstg + row * 128 + (((ks * 2 + k_hi) ^ (row & 7)) * 16);
                    uint32_t b0, b1, b2, b3;
                    LDM_X4(b0, b1, b2, b3, addr);
                    uint32_t bA[2] = { b0, b1 }, bB[2] = { b2, b3 };
#pragma unroll
                    for (int mi2 = 0; mi2 < 2; mi2++) {
                        mma16(s[mi2][2 * p], qa[mi2][ks], bA);
                        mma16(s[mi2][2 * p + 1], qa[mi2][ks], bB);
                    }
                }
            }

            // causal mask (diagonal tiles only)
            if (j0 + 63 > row_base) {
#pragma unroll
                for (int mi2 = 0; mi2 < 2; mi2++) {
                    int ra = row_a0 + mi2 * 16, rb = ra + 8;
#pragma unroll
                    for (int ni = 0; ni < 8; ni++) {
                        int c0 = j0 + ni * 8 + cc;
                        if (c0     > ra) s[mi2][ni][0] = -1e30f;
                        if (c0 + 1 > ra) s[mi2][ni][1] = -1e30f;
                        if (c0     > rb) s[mi2][ni][2] = -1e30f;
                        if (c0 + 1 > rb) s[mi2][ni][3] = -1e30f;
                    }
                }
            }

            // P = exp2(S), and row sums on the scalar pipes
#pragma unroll
            for (int mi2 = 0; mi2 < 2; mi2++) {
                float sa = 0.f, sb = 0.f;
#pragma unroll
                for (int ni = 0; ni < 8; ni++) {
                    s[mi2][ni][0] = exp2f(s[mi2][ni][0]);
                    s[mi2][ni][1] = exp2f(s[mi2][ni][1]);
                    sa += s[mi2][ni][0] + s[mi2][ni][1];
                    s[mi2][ni][2] = exp2f(s[mi2][ni][2]);
                    s[mi2][ni][3] = exp2f(s[mi2][ni][3]);
                    sb += s[mi2][ni][2] + s[mi2][ni][3];
                }
                sa += __shfl_xor_sync(0xffffffffu, sa, 1);
                sa += __shfl_xor_sync(0xffffffffu, sa, 2);
                sb += __shfl_xor_sync(0xffffffffu, sb, 1);
                sb += __shfl_xor_sync(0xffffffffu, sb, 2);
                l[mi2][0] += sa;
                l[mi2][1] += sb;
            }

            // O += P V
#pragma unroll
            for (int ks = 0; ks < 4; ks++) {
                uint32_t pa[2][4];
#pragma unroll
                for (int mi2 = 0; mi2 < 2; mi2++) {
                    pa[mi2][0] = pack_h2(s[mi2][2 * ks][0], s[mi2][2 * ks][1]);
                    pa[mi2][1] = pack_h2(s[mi2][2 * ks][2], s[mi2][2 * ks][3]);
                    pa[mi2][2] = pack_h2(s[mi2][2 * ks + 1][0], s[mi2][2 * ks + 1][1]);
                    pa[mi2][3] = pack_h2(s[mi2][2 * ks + 1][2], s[mi2][2 * ks + 1][3]);
                }
                int row = v_row + ks * 16;
                uint32_t rowoff = vstg + row * 128;
                int rlow = row & 7;
#pragma unroll
                for (int p = 0; p < 4; p++) {
                    uint32_t addr = rowoff + (((2 * p + v_hi) ^ rlow) * 16);
                    uint32_t b0, b1, b2, b3;
                    LDM_X4_T(b0, b1, b2, b3, addr);
                    uint32_t bA[2] = { b0, b1 }, bB[2] = { b2, b3 };
#pragma unroll
                    for (int mi2 = 0; mi2 < 2; mi2++) {
                        mma16(o[mi2][2 * p], pa[mi2], bA);
                        mma16(o[mi2][2 * p + 1], pa[mi2], bB);
                    }
                }
            }
        }
        st++; if (st >= 3) st -= 3;
    }

    // normalize + write g_y fp16 [B,T,C]
#pragma unroll
    for (int mi2 = 0; mi2 < 2; mi2++) {
        const float ia = 1.f / l[mi2][0], ib = 1.f / l[mi2][1];
        int ra = row_a0 + mi2 * 16, rb = ra + 8;
        __half* yra = g_y + (size_t)(bb * Tq + ra) * Cq + h * Dq;
        __half* yrb = g_y + (size_t)(bb * Tq + rb) * Cq + h * Dq;
#pragma unroll
        for (int ni = 0; ni < 8; ni++) {
            int cf = ni * 8 + cc;
            *(uint32_t*)(yra + cf) = pack_h2(o[mi2][ni][0] * ia, o[mi2][ni][1] * ia);
            *(uint32_t*)(yrb + cf) = pack_h2(o[mi2][ni][2] * ib, o[mi2][ni][3] * ib);
        }
    }
}

// ---------------------------------------------------------------------------
extern "C" void kernel_launch(void* const* d_in, const int* in_sizes, int n_in,
                              void* d_out, int out_size) {
    const float* x    = (const float*)d_in[0];   // [B,T,C]
    const float* Wqkv = (const float*)d_in[1];   // [C,3C]
    const float* Wo   = (const float*)d_in[2];   // [C,C]
    const float* bo   = (const float*)d_in[3];   // [C]
    float* out = (float*)d_out;                  // [B,T,C]

    static bool attr_done = false;
    if (!attr_done) {
        cudaFuncSetAttribute(gemm_mma, cudaFuncAttributeMaxDynamicSharedMemorySize,
                             GEMM_SMEM);
        cudaFuncSetAttribute(flash_mma, cudaFuncAttributeMaxDynamicSharedMemorySize,
                             FLASH_SMEM);
        attr_done = true;
    }

    __half* wqkv_h; cudaGetSymbolAddress((void**)&wqkv_h, g_wqkv_h);
    __half* wo_h;   cudaGetSymbolAddress((void**)&wo_h,   g_wo_h);
    __half* xr;     cudaGetSymbolAddress((void**)&xr,     g_xr);
    __half* yptr;   cudaGetSymbolAddress((void**)&yptr,   g_y);

    // Preprocess: single fused fp16 rounding pass (16 elems/thread)
    round_all<<<NF16_TOT / 256, 256>>>(x, Wqkv, Wo);

    // QKV projection (CTA tile 128x256, BK=128)
    gemm_mma<<<dim3(N_QKV / 256, Mrows / 128), 256, GEMM_SMEM>>>(
        xr, wqkv_h, Cq, N_QKV, 0, nullptr, nullptr);

    // Attention (128 q-rows/CTA, 4 warps x 32 rows)
    flash_mma<<<dim3(Tq / 128, Bq * Hq), 128, FLASH_SMEM>>>();

    // Output projection
    gemm_mma<<<dim3(Cq / 256, Mrows / 128), 256, GEMM_SMEM>>>(
        yptr, wo_h, Cq, Cq, 1, bo, out);
}